// round 14
// baseline (speedup 1.0000x reference)
#include <cuda_runtime.h>
#include <math.h>
#include <stdint.h>

// Problem constants
#define TT   2048
#define BB   32
#define ICC  512
#define HCC  512
#define LLL  2

// Recurrence: cluster = 8 CTAs = one batch group (2 batches); CTA owns 64 ch.
#define CSIZE 8
#define NCTA  128
#define RTH   256
#define BPG   2
#define CPG   64
#define QST   132            // padded quarter stride (128 + 4) -> conflict-free LDS

// Projection GEMM config
#define PBM 128
#define PBN 128
#define PBK 16
#define PLD (PBM + 4)

// ---------------------------------------------------------------------------
// Scratch (static device globals: allocation-free per harness rules)
// ---------------------------------------------------------------------------
__device__ float g_xproj[(size_t)TT * BB * HCC];
__device__ float g_ys0[(size_t)TT * BB * HCC];

// ---------------------------------------------------------------------------
// Packed f32x2 helpers
// ---------------------------------------------------------------------------
__device__ __forceinline__ void fma2(unsigned long long& acc,
                                     unsigned long long a, unsigned long long b) {
    asm("fma.rn.f32x2 %0, %1, %2, %0;" : "+l"(acc) : "l"(a), "l"(b));
}
__device__ __forceinline__ unsigned long long dup2(float x) {
    unsigned long long d;
    asm("mov.b64 %0, {%1, %1};" : "=l"(d) : "f"(x));
    return d;
}
__device__ __forceinline__ unsigned long long add2(unsigned long long a,
                                                   unsigned long long b) {
    unsigned long long r;
    asm("add.rn.f32x2 %0, %1, %2;" : "=l"(r) : "l"(a), "l"(b));
    return r;
}
__device__ __forceinline__ float2 unpk(unsigned long long v) {
    float2 r;
    asm("mov.b64 {%0, %1}, %2;" : "=f"(r.x), "=f"(r.y) : "l"(v));
    return r;
}

// ---------------------------------------------------------------------------
// Cluster / mbarrier helpers (field-verified in earlier rounds)
// ---------------------------------------------------------------------------
__device__ __forceinline__ uint32_t smem_u32(const void* p) {
    uint32_t a;
    asm("{ .reg .u64 t; cvta.to.shared.u64 t, %1; cvt.u32.u64 %0, t; }"
        : "=r"(a) : "l"(p));
    return a;
}
__device__ __forceinline__ uint32_t mapa_u32(uint32_t a, uint32_t rank) {
    uint32_t r;
    asm("mapa.shared::cluster.u32 %0, %1, %2;" : "=r"(r) : "r"(a), "r"(rank));
    return r;
}
__device__ __forceinline__ void st_cluster_f4(uint32_t a, float4 v) {
    asm volatile("st.shared::cluster.v4.f32 [%0], {%1,%2,%3,%4};"
                 :: "r"(a), "f"(v.x), "f"(v.y), "f"(v.z), "f"(v.w) : "memory");
}
__device__ __forceinline__ void mbar_init(uint32_t a, uint32_t cnt) {
    asm volatile("mbarrier.init.shared.b64 [%0], %1;" :: "r"(a), "r"(cnt) : "memory");
}
__device__ __forceinline__ void mbar_arrive_remote(uint32_t a) {
    asm volatile("mbarrier.arrive.release.cluster.shared::cluster.b64 _, [%0];"
                 :: "r"(a) : "memory");
}
__device__ __forceinline__ void mbar_wait_parity(uint32_t a, uint32_t parity) {
    uint32_t done;
    asm volatile(
        "{\n\t.reg .pred p;\n\t"
        "mbarrier.try_wait.parity.acquire.cluster.shared::cta.b64 p, [%1], %2;\n\t"
        "selp.b32 %0, 1, 0, p;\n\t}"
        : "=r"(done) : "r"(a), "r"(parity) : "memory");
    if (!done) {
        asm volatile(
            "{\n\t.reg .pred P1;\n\t"
            "W_%=:\n\t"
            "mbarrier.try_wait.parity.acquire.cluster.shared::cta.b64 P1, [%0], %1, 0x989680;\n\t"
            "@P1 bra.uni D_%=;\n\t"
            "bra.uni W_%=;\n\t"
            "D_%=:\n\t}"
            :: "r"(a), "r"(parity) : "memory");
    }
}
#define CL_SYNC() do { \
    asm volatile("barrier.cluster.arrive.aligned;" ::: "memory"); \
    asm volatile("barrier.cluster.wait.aligned;"   ::: "memory"); } while (0)

// ---------------------------------------------------------------------------
// Projection GEMM with packed FFMA2 (unchanged from R12)
// ---------------------------------------------------------------------------
__global__ __launch_bounds__(256, 2)
void proj_kernel(const float* __restrict__ Xin, const float* __restrict__ Wp,
                 const float* __restrict__ bp, int use_internal)
{
    const float* A = use_internal ? (const float*)g_ys0 : Xin;
    __shared__ float As[PBK][PLD];
    __shared__ float Bs[PBK][PLD];

    const int t  = threadIdx.x;
    const int m0 = blockIdx.y * PBM;
    const int n0 = blockIdx.x * PBN;
    const int lr = t >> 1;
    const int lc = (t & 1) << 3;
    const int tx = t & 15;
    const int ty = t >> 4;

    unsigned long long acc2[8][4];
#pragma unroll
    for (int i = 0; i < 8; i++)
#pragma unroll
        for (int j = 0; j < 4; j++) acc2[i][j] = 0ULL;

    const float* Ag = A  + (size_t)(m0 + lr) * ICC;
    const float* Bg = Wp + (size_t)(n0 + lr) * ICC;

    for (int k0 = 0; k0 < ICC; k0 += PBK) {
        float4 a0 = __ldg((const float4*)(Ag + k0 + lc));
        float4 a1 = __ldg((const float4*)(Ag + k0 + lc + 4));
        float4 b0 = __ldg((const float4*)(Bg + k0 + lc));
        float4 b1 = __ldg((const float4*)(Bg + k0 + lc + 4));
        As[lc+0][lr] = a0.x; As[lc+1][lr] = a0.y; As[lc+2][lr] = a0.z; As[lc+3][lr] = a0.w;
        As[lc+4][lr] = a1.x; As[lc+5][lr] = a1.y; As[lc+6][lr] = a1.z; As[lc+7][lr] = a1.w;
        Bs[lc+0][lr] = b0.x; Bs[lc+1][lr] = b0.y; Bs[lc+2][lr] = b0.z; Bs[lc+3][lr] = b0.w;
        Bs[lc+4][lr] = b1.x; Bs[lc+5][lr] = b1.y; Bs[lc+6][lr] = b1.z; Bs[lc+7][lr] = b1.w;
        __syncthreads();
#pragma unroll
        for (int k = 0; k < PBK; k++) {
            float4 am0 = *(const float4*)&As[k][ty * 8];
            float4 am1 = *(const float4*)&As[k][ty * 8 + 4];
            ulonglong2 bu0 = *(const ulonglong2*)&Bs[k][tx * 8];
            ulonglong2 bu1 = *(const ulonglong2*)&Bs[k][tx * 8 + 4];
            float am[8] = {am0.x, am0.y, am0.z, am0.w, am1.x, am1.y, am1.z, am1.w};
#pragma unroll
            for (int i = 0; i < 8; i++) {
                unsigned long long ad = dup2(am[i]);
                fma2(acc2[i][0], ad, bu0.x);
                fma2(acc2[i][1], ad, bu0.y);
                fma2(acc2[i][2], ad, bu1.x);
                fma2(acc2[i][3], ad, bu1.y);
            }
        }
        __syncthreads();
    }

    float4 bv0 = __ldg((const float4*)(bp + n0 + tx * 8));
    float4 bv1 = __ldg((const float4*)(bp + n0 + tx * 8 + 4));
#pragma unroll
    for (int i = 0; i < 8; i++) {
        size_t row = (size_t)(m0 + ty * 8 + i);
        float2 p0 = unpk(acc2[i][0]);
        float2 p1 = unpk(acc2[i][1]);
        float2 p2 = unpk(acc2[i][2]);
        float2 p3 = unpk(acc2[i][3]);
        float4 o0 = make_float4(p0.x + bv0.x, p0.y + bv0.y, p1.x + bv0.z, p1.y + bv0.w);
        float4 o1 = make_float4(p2.x + bv1.x, p2.y + bv1.y, p3.x + bv1.z, p3.y + bv1.w);
        *(float4*)&g_xproj[row * HCC + n0 + tx * 8]     = o0;
        *(float4*)&g_xproj[row * HCC + n0 + tx * 8 + 4] = o1;
    }
}

// ---------------------------------------------------------------------------
// Recurrence: WARP-AUTONOMOUS. Cluster rank = cg (0..7). CTA(bg,cg):
// batches {2bg,2bg+1}, channels [64cg,+64). Warp w owns channels [8w,8w+8).
// Lane (c=l&7, q=l>>3): dot over k-quarter [128q,+128) for channel c, both
// batches (128 FFMA2, FFMA2-packed weights in regs). k-reduction via 2x
// shfl.bfly (no smem, no syncthreads). Lane's batch = q&1; tanh; per-warp
// 16-float staging + syncwarp; ONE remote st.v4 per lane (piece l>>3 to rank
// l&7); one release-arrive per (warp,rank) -> mbar expect 64. h staging is
// quarter-padded (QST=132) so the dot's 4-address LDS.128 is conflict-free.
// NO __syncthreads in the hot loop; the only sync is the mbar wait.
// ---------------------------------------------------------------------------
__global__ __launch_bounds__(RTH, 1) __cluster_dims__(CSIZE, 1, 1)
void rec_kernel(const float* __restrict__ Wh, const float* __restrict__ bh,
                float* __restrict__ out_ys, float* __restrict__ out_hs,
                int write_internal)
{
    __shared__ float hs[2][8 * QST];     // [buf][(b*4+q)*QST + rem]
    __shared__ float hnw[8][16];         // per-warp staging [b*8 + c]
    __shared__ __align__(8) unsigned long long mbar[2];

    const int t    = threadIdx.x;
    const int bid  = blockIdx.x;
    const int bg   = bid >> 3;
    const int cg   = bid & 7;
    const int b0   = bg * BPG;
    const int c0   = cg * CPG;
    const int w    = t >> 5;
    const int l    = t & 31;
    const int c    = l & 7;        // channel within warp's 8
    const int q    = l >> 3;       // k-quarter 0..3
    const int bsel = q & 1;        // this lane's output batch
    const int gc   = c0 + w * 8 + c;   // global channel

    float* ysp = write_internal ? (float*)g_ys0 : out_ys;

    // Step-invariant weights: Wh[gc][128q .. +128) as 32 ulonglong2 (128 regs).
    ulonglong2 wr2[32];
    {
        const ulonglong2* wsrc =
            (const ulonglong2*)(Wh + (size_t)gc * HCC + q * 128);
#pragma unroll
        for (int j = 0; j < 32; j++) wr2[j] = wsrc[j];
    }

    const uint32_t mb0  = smem_u32(&mbar[0]);
    const uint32_t mb1  = smem_u32(&mbar[1]);
    const uint32_t hsb0 = smem_u32(&hs[0][0]);
    const uint32_t hsb1 = smem_u32(&hs[1][0]);

    if (t == 0) { mbar_init(mb0, 64); mbar_init(mb1, 64); }
    for (int i = t; i < 8 * QST; i += RTH) hs[0][i] = 0.f;   // h0 = 0
    __syncthreads();
    CL_SYNC();   // mbarriers live cluster-wide before any remote op

    // Push-side addresses. Piece p = l>>3 of warp's 16 outputs goes to rank
    // l&7: p -> (b = p>>1, half = p&1); warp block rem0 = (c0+8w)&127 within
    // quarter qq = (c0+8w)>>7. Byte offset in target hs buffer:
    const int qq   = (c0 + 8 * w) >> 7;
    const int rem0 = (c0 + 8 * w) & 127;
    const int pp   = l >> 3;
    const uint32_t poff =
        (uint32_t)((((pp >> 1) * 4 + qq) * QST + rem0 + 4 * (pp & 1)) * 4);
    const uint32_t prank = (uint32_t)(l & 7);
    const uint32_t rh0 = mapa_u32(hsb0, prank) + poff;
    const uint32_t rh1 = mapa_u32(hsb1, prank) + poff;
    const uint32_t rm0 = mapa_u32(mb0, (uint32_t)(l & 7));
    const uint32_t rm1 = mapa_u32(mb1, (uint32_t)(l & 7));

    const float bhv = __ldg(bh + gc);

    // xproj pipeline: preload step 0.
    const float* xbase = g_xproj + (size_t)(b0 + bsel) * HCC + gc;
    float xpv = __ldg(xbase);

    int ph0 = 0, ph1 = 0;

    for (int s = 0; s < TT; s++) {
        // Prefetch next step's xproj (full-step distance).
        float xnext = 0.f;
        if (s + 1 < TT)
            xnext = __ldg(xbase + (size_t)(s + 1) * (BB * HCC));

        if (s > 0) {
            if (s & 1) { mbar_wait_parity(mb1, (uint32_t)ph1); ph1 ^= 1; }
            else       { mbar_wait_parity(mb0, (uint32_t)ph0); ph0 ^= 1; }
        }

        // Dot: channel c, k-quarter q, both batches. Conflict-free LDS.128.
        const float* hb = hs[s & 1];
        const ulonglong2* hb0 = (const ulonglong2*)(hb + q * QST);
        const ulonglong2* hb1 = (const ulonglong2*)(hb + (4 + q) * QST);
        unsigned long long a0a = 0ULL, a0b = 0ULL, a1a = 0ULL, a1b = 0ULL;
#pragma unroll
        for (int j = 0; j < 32; j++) {
            ulonglong2 wv = wr2[j];
            ulonglong2 h0 = hb0[j];
            ulonglong2 h1 = hb1[j];
            fma2(a0a, wv.x, h0.x);
            fma2(a0b, wv.y, h0.y);
            fma2(a1a, wv.x, h1.x);
            fma2(a1b, wv.y, h1.y);
        }
        float2 f0 = unpk(add2(a0a, a0b));
        float2 f1 = unpk(add2(a1a, a1b));
        float p0 = f0.x + f0.y;          // partial, batch 0
        float p1 = f1.x + f1.y;          // partial, batch 1

        // k-reduce across the 4 q-lanes of this channel (stride 8).
        p0 += __shfl_xor_sync(0xffffffffu, p0, 8);
        p1 += __shfl_xor_sync(0xffffffffu, p1, 8);
        p0 += __shfl_xor_sync(0xffffffffu, p0, 16);
        p1 += __shfl_xor_sync(0xffffffffu, p1, 16);

        float hn = tanhf((bsel ? p1 : p0) + xpv + bhv);

        // Stage warp's 16 outputs (lanes l<16 write; l>=16 are duplicates).
        if (l < 16) hnw[w][bsel * 8 + c] = hn;
        __syncwarp();

        // Push: one remote st.v4 per lane (piece pp -> rank l&7).
        if (s + 1 < TT) {
            float4 v = *(const float4*)&hnw[w][4 * pp];
            if ((s + 1) & 1) st_cluster_f4(rh1, v);
            else             st_cluster_f4(rh0, v);
            __syncwarp();
            if (l < 8) {
                if ((s + 1) & 1) mbar_arrive_remote(rm1);
                else             mbar_arrive_remote(rm0);
            }
        }

        // Off critical path: vectorized ys (+ final h) stores, lanes 0-3.
        if (l < 4) {
            float4 v = *(const float4*)&hnw[w][4 * l];
            size_t oi = (size_t)(b0 + (l >> 1)) * HCC + c0 + 8 * w + 4 * (l & 1);
            *(float4*)(ysp + (size_t)s * (BB * HCC) + oi) = v;
            if (s == TT - 1) *(float4*)(out_hs + oi) = v;
        }

        xpv = xnext;
    }

    CL_SYNC();   // no CTA exits while peers' remote ops may be in flight
}

// ---------------------------------------------------------------------------
// Output layout: [hs (L,B,HC) | inp (T,B,HC)]
// ---------------------------------------------------------------------------
extern "C" void kernel_launch(void* const* d_in, const int* in_sizes, int n_in,
                              void* d_out, int out_size) {
    const float* x  = (const float*)d_in[0];
    const float* Wi = (const float*)d_in[1];
    const float* bi = (const float*)d_in[2];
    const float* Wh = (const float*)d_in[3];
    const float* bh = (const float*)d_in[4];
    float* out = (float*)d_out;

    dim3 pg(HCC / PBN, (TT * BB) / PBM);  // (4, 512)

    // Layer 0
    proj_kernel<<<pg, 256>>>(x, Wi, bi, 0);
    rec_kernel<<<NCTA, RTH>>>(Wh, bh, nullptr, out, 1);

    // Layer 1
    proj_kernel<<<pg, 256>>>(x, Wi + HCC * ICC, bi + HCC, 1);
    rec_kernel<<<NCTA, RTH>>>(Wh + HCC * HCC, bh + HCC,
                              out + (size_t)LLL * BB * HCC,  // inp region
                              out + BB * HCC,                // hs[1]
                              0);
}

// round 15
// speedup vs baseline: 1.6137x; 1.6137x over previous
#include <cuda_runtime.h>
#include <math.h>
#include <stdint.h>

// Problem constants
#define TT   2048
#define BB   32
#define ICC  512
#define HCC  512
#define LLL  2

// Fused recurrence: 8 clusters x 16 CTAs. Cluster = 4 batches; CTA = 32 ch.
#define CS    16
#define NCTA  128
#define RTH   256
#define BPG   4
#define CPG   32

// Dynamic smem layout (bytes)
#define OFF_WI1   0
#define OFF_WH1   66048                 // 32 rows * 129 f4 * 16B
#define OFF_H0    132096                // float[2][2048]
#define OFF_H1    148480                // float[2][2048]
#define OFF_RED   164864                // float[3][1024]
#define OFF_HNL0  177152                // float[128]
#define OFF_HNL1  177664                // float[128]
#define FSMEM     178176

// Projection GEMM config
#define PBM 128
#define PBN 128
#define PBK 16
#define PLD (PBM + 4)

__device__ float g_xproj[(size_t)TT * BB * HCC];

// ---------------------------------------------------------------------------
// Packed f32x2 helpers
// ---------------------------------------------------------------------------
__device__ __forceinline__ void fma2(unsigned long long& acc,
                                     unsigned long long a, unsigned long long b) {
    asm("fma.rn.f32x2 %0, %1, %2, %0;" : "+l"(acc) : "l"(a), "l"(b));
}
__device__ __forceinline__ unsigned long long dup2(float x) {
    unsigned long long d;
    asm("mov.b64 %0, {%1, %1};" : "=l"(d) : "f"(x));
    return d;
}
__device__ __forceinline__ float2 unpk(unsigned long long v) {
    float2 r;
    asm("mov.b64 {%0, %1}, %2;" : "=f"(r.x), "=f"(r.y) : "l"(v));
    return r;
}

// ---------------------------------------------------------------------------
// Cluster / mbarrier helpers (field-verified R9-R12)
// ---------------------------------------------------------------------------
__device__ __forceinline__ uint32_t smem_u32(const void* p) {
    uint32_t a;
    asm("{ .reg .u64 t; cvta.to.shared.u64 t, %1; cvt.u32.u64 %0, t; }"
        : "=r"(a) : "l"(p));
    return a;
}
__device__ __forceinline__ uint32_t mapa_u32(uint32_t a, uint32_t rank) {
    uint32_t r;
    asm("mapa.shared::cluster.u32 %0, %1, %2;" : "=r"(r) : "r"(a), "r"(rank));
    return r;
}
__device__ __forceinline__ void st_cluster_f4(uint32_t a, float4 v) {
    asm volatile("st.shared::cluster.v4.f32 [%0], {%1,%2,%3,%4};"
                 :: "r"(a), "f"(v.x), "f"(v.y), "f"(v.z), "f"(v.w) : "memory");
}
__device__ __forceinline__ void mbar_init(uint32_t a, uint32_t cnt) {
    asm volatile("mbarrier.init.shared.b64 [%0], %1;" :: "r"(a), "r"(cnt) : "memory");
}
__device__ __forceinline__ void mbar_arrive_remote(uint32_t a) {
    asm volatile("mbarrier.arrive.release.cluster.shared::cluster.b64 _, [%0];"
                 :: "r"(a) : "memory");
}
__device__ __forceinline__ void mbar_wait_parity(uint32_t a, uint32_t parity) {
    uint32_t done;
    asm volatile(
        "{\n\t.reg .pred p;\n\t"
        "mbarrier.try_wait.parity.acquire.cluster.shared::cta.b64 p, [%1], %2;\n\t"
        "selp.b32 %0, 1, 0, p;\n\t}"
        : "=r"(done) : "r"(a), "r"(parity) : "memory");
    if (!done) {
        asm volatile(
            "{\n\t.reg .pred P1;\n\t"
            "W_%=:\n\t"
            "mbarrier.try_wait.parity.acquire.cluster.shared::cta.b64 P1, [%0], %1, 0x989680;\n\t"
            "@P1 bra.uni D_%=;\n\t"
            "bra.uni W_%=;\n\t"
            "D_%=:\n\t}"
            :: "r"(a), "r"(parity) : "memory");
    }
}
#define CL_SYNC() do { \
    asm volatile("barrier.cluster.arrive.aligned;" ::: "memory"); \
    asm volatile("barrier.cluster.wait.aligned;"   ::: "memory"); } while (0)

// ---------------------------------------------------------------------------
// Projection GEMM (R12-proven, FFMA2). Only layer 0 now.
// ---------------------------------------------------------------------------
__global__ __launch_bounds__(256, 2)
void proj_kernel(const float* __restrict__ Xin, const float* __restrict__ Wp,
                 const float* __restrict__ bp)
{
    __shared__ float As[PBK][PLD];
    __shared__ float Bs[PBK][PLD];

    const int t  = threadIdx.x;
    const int m0 = blockIdx.y * PBM;
    const int n0 = blockIdx.x * PBN;
    const int lr = t >> 1;
    const int lc = (t & 1) << 3;
    const int tx = t & 15;
    const int ty = t >> 4;

    unsigned long long acc2[8][4];
#pragma unroll
    for (int i = 0; i < 8; i++)
#pragma unroll
        for (int j = 0; j < 4; j++) acc2[i][j] = 0ULL;

    const float* Ag = Xin + (size_t)(m0 + lr) * ICC;
    const float* Bg = Wp  + (size_t)(n0 + lr) * ICC;

    for (int k0 = 0; k0 < ICC; k0 += PBK) {
        float4 a0 = __ldg((const float4*)(Ag + k0 + lc));
        float4 a1 = __ldg((const float4*)(Ag + k0 + lc + 4));
        float4 b0 = __ldg((const float4*)(Bg + k0 + lc));
        float4 b1 = __ldg((const float4*)(Bg + k0 + lc + 4));
        As[lc+0][lr] = a0.x; As[lc+1][lr] = a0.y; As[lc+2][lr] = a0.z; As[lc+3][lr] = a0.w;
        As[lc+4][lr] = a1.x; As[lc+5][lr] = a1.y; As[lc+6][lr] = a1.z; As[lc+7][lr] = a1.w;
        Bs[lc+0][lr] = b0.x; Bs[lc+1][lr] = b0.y; Bs[lc+2][lr] = b0.z; Bs[lc+3][lr] = b0.w;
        Bs[lc+4][lr] = b1.x; Bs[lc+5][lr] = b1.y; Bs[lc+6][lr] = b1.z; Bs[lc+7][lr] = b1.w;
        __syncthreads();
#pragma unroll
        for (int k = 0; k < PBK; k++) {
            float4 am0 = *(const float4*)&As[k][ty * 8];
            float4 am1 = *(const float4*)&As[k][ty * 8 + 4];
            ulonglong2 bu0 = *(const ulonglong2*)&Bs[k][tx * 8];
            ulonglong2 bu1 = *(const ulonglong2*)&Bs[k][tx * 8 + 4];
            float am[8] = {am0.x, am0.y, am0.z, am0.w, am1.x, am1.y, am1.z, am1.w};
#pragma unroll
            for (int i = 0; i < 8; i++) {
                unsigned long long ad = dup2(am[i]);
                fma2(acc2[i][0], ad, bu0.x);
                fma2(acc2[i][1], ad, bu0.y);
                fma2(acc2[i][2], ad, bu1.x);
                fma2(acc2[i][3], ad, bu1.y);
            }
        }
        __syncthreads();
    }

    float4 bv0 = __ldg((const float4*)(bp + n0 + tx * 8));
    float4 bv1 = __ldg((const float4*)(bp + n0 + tx * 8 + 4));
#pragma unroll
    for (int i = 0; i < 8; i++) {
        size_t row = (size_t)(m0 + ty * 8 + i);
        float2 p0 = unpk(acc2[i][0]);
        float2 p1 = unpk(acc2[i][1]);
        float2 p2 = unpk(acc2[i][2]);
        float2 p3 = unpk(acc2[i][3]);
        float4 o0 = make_float4(p0.x + bv0.x, p0.y + bv0.y, p1.x + bv0.z, p1.y + bv0.w);
        float4 o1 = make_float4(p2.x + bv1.x, p2.y + bv1.y, p3.x + bv1.z, p3.y + bv1.w);
        *(float4*)&g_xproj[row * HCC + n0 + tx * 8]     = o0;
        *(float4*)&g_xproj[row * HCC + n0 + tx * 8 + 4] = o1;
    }
}

// ---------------------------------------------------------------------------
// Fused 2-layer recurrence. 8 clusters of 16 CTAs. CTA(bg,rank): batches
// [4bg,4bg+4), channels [32r,32r+32). Superstep s in [0,TT]:
//   A: h0[s]   = tanh(xp0[s] + Wh0 . H0[s-1])          (s < TT)
//   B: xp1     = bi1 + Wi1 . H0[s-1]                   (s >= 1; same staged H0!)
//   C: h1[s-1] = tanh(xp1 + bh1 + Wh1 . H1[s-2])       (s >= 1)
// Warp w owns k-range [64w,64w+64); lane = channel; 4 batches per thread.
// Wh0 in regs (16 u2); Wi1/Wh1 in pad-129 smem (conflict-free LDS.128).
// Exchange: push h0-slice + h1-slice to all 16 ranks (warp w -> ranks w,w+8),
// one release-arrive per (source CTA, target) -> mbar expect 16. R12 pattern.
// ---------------------------------------------------------------------------
__global__ __launch_bounds__(RTH, 1)
void fused_kernel(const float* __restrict__ Wi, const float* __restrict__ Wh,
                  const float* __restrict__ bi, const float* __restrict__ bh,
                  float* __restrict__ out)
{
    extern __shared__ char sm[];
    float4* wi1s = (float4*)(sm + OFF_WI1);
    float4* wh1s = (float4*)(sm + OFF_WH1);
    float*  H0   = (float*)(sm + OFF_H0);
    float*  H1   = (float*)(sm + OFF_H1);
    float*  redA = (float*)(sm + OFF_RED);
    float*  redB = redA + 1024;
    float*  redC = redA + 2048;
    float*  hnl0 = (float*)(sm + OFF_HNL0);
    float*  hnl1 = (float*)(sm + OFF_HNL1);
    __shared__ __align__(8) unsigned long long mbar[2];

    const int t    = threadIdx.x;
    const int bid  = blockIdx.x;
    const int bg   = bid >> 4;
    const int rank = bid & 15;
    const int b0   = bg * BPG;
    const int c0   = rank * CPG;
    const int w    = t >> 5;       // k-slice [64w, 64w+64)
    const int l    = t & 31;       // channel within CTA
    const int gc   = c0 + l;

    const float* Wh0g = Wh;
    const float* Wh1g = Wh + (size_t)HCC * HCC;
    const float* Wi1g = Wi + (size_t)HCC * ICC;
    float* out_hs0 = out;
    float* out_hs1 = out + BB * HCC;
    float* out_inp = out + (size_t)LLL * BB * HCC;

    // Wh0 slice -> registers: 16 ulonglong2 (64 floats).
    ulonglong2 wr0[16];
    {
        const ulonglong2* p = (const ulonglong2*)(Wh0g + (size_t)gc * HCC + w * 64);
#pragma unroll
        for (int j = 0; j < 16; j++) wr0[j] = p[j];
    }
    // Wi1 / Wh1 slices -> pad-129 smem (bank-conflict-free by construction).
    {
        const float4* si = (const float4*)Wi1g + (size_t)c0 * (HCC / 4);
        const float4* sh = (const float4*)Wh1g + (size_t)c0 * (HCC / 4);
        for (int idx = t; idx < CPG * (HCC / 4); idx += RTH) {
            int row = idx >> 7, k4 = idx & 127;
            wi1s[row * 129 + k4] = __ldg(si + idx);
            wh1s[row * 129 + k4] = __ldg(sh + idx);
        }
    }
    // Zero step-0 staging; init mbarriers.
    for (int i = t; i < 2048; i += RTH) { H0[i] = 0.f; H1[i] = 0.f; }
    if (t == 0) { mbar_init(smem_u32(&mbar[0]), CS); mbar_init(smem_u32(&mbar[1]), CS); }
    __syncthreads();
    CL_SYNC();

    // Push-side precomputed addresses: warp w targets ranks w and w+8; lane l
    // carries f4 #l of each 128-float slice -> b_loc = l>>3, ch4 = l&7.
    const uint32_t mb0 = smem_u32(&mbar[0]);
    const uint32_t mb1 = smem_u32(&mbar[1]);
    const uint32_t h0a = smem_u32(H0);
    const uint32_t h1a = smem_u32(H1);
    const uint32_t soff = (uint32_t)(((l >> 3) * HCC + c0 + 4 * (l & 7)) * 4);
    const uint32_t rA = (uint32_t)w, rB = (uint32_t)(w + 8);
    const uint32_t h0A0 = mapa_u32(h0a, rA) + soff, h0A1 = h0A0 + 8192;
    const uint32_t h0B0 = mapa_u32(h0a, rB) + soff, h0B1 = h0B0 + 8192;
    const uint32_t h1A0 = mapa_u32(h1a, rA) + soff, h1A1 = h1A0 + 8192;
    const uint32_t h1B0 = mapa_u32(h1a, rB) + soff, h1B1 = h1B0 + 8192;
    const uint32_t mA0 = mapa_u32(mb0, rA), mA1 = mapa_u32(mb1, rA);
    const uint32_t mB0 = mapa_u32(mb0, rB), mB1 = mapa_u32(mb1, rB);

    // Epilogue biases (t<128): b = t>>5, ch = t&31.
    float bh0v = 0.f, bi1v = 0.f, bh1v = 0.f;
    if (t < 128) {
        bh0v = __ldg(bh + c0 + (t & 31));
        bi1v = __ldg(bi + HCC + c0 + (t & 31));
        bh1v = __ldg(bh + HCC + c0 + (t & 31));
    }

    const float4* wip  = wi1s + l * 129 + w * 16;
    const float4* wh1p = wh1s + l * 129 + w * 16;

    int ph0 = 0, ph1 = 0;

    for (int s = 0; s <= TT; s++) {
        // Prefetch xproj0[s] (before the wait).
        float xp0v = 0.f;
        if (t < 128 && s < TT)
            xp0v = __ldg(&g_xproj[(size_t)s * (BB * HCC) +
                                  (size_t)(b0 + (t >> 5)) * HCC + c0 + (t & 31)]);

        if (s > 0) {
            if (s & 1) { mbar_wait_parity(mb1, (uint32_t)ph1); ph1 ^= 1; }
            else       { mbar_wait_parity(mb0, (uint32_t)ph0); ph0 ^= 1; }
        }

        // Triple dot: channel l, k in [64w,64w+64), 4 batches each.
        const float* h0b = H0 + (s & 1) * 2048 + w * 64;
        const float* h1b = H1 + (s & 1) * 2048 + w * 64;
        const ulonglong2* h0p0 = (const ulonglong2*)(h0b);
        const ulonglong2* h0p1 = (const ulonglong2*)(h0b + HCC);
        const ulonglong2* h0p2 = (const ulonglong2*)(h0b + 2 * HCC);
        const ulonglong2* h0p3 = (const ulonglong2*)(h0b + 3 * HCC);
        const ulonglong2* h1p0 = (const ulonglong2*)(h1b);
        const ulonglong2* h1p1 = (const ulonglong2*)(h1b + HCC);
        const ulonglong2* h1p2 = (const ulonglong2*)(h1b + 2 * HCC);
        const ulonglong2* h1p3 = (const ulonglong2*)(h1b + 3 * HCC);

        unsigned long long aA0=0,aA1=0,aA2=0,aA3=0;
        unsigned long long aB0=0,aB1=0,aB2=0,aB3=0;
        unsigned long long aC0=0,aC1=0,aC2=0,aC3=0;
#pragma unroll
        for (int j = 0; j < 16; j++) {
            ulonglong2 w0 = wr0[j];
            ulonglong2 wi2 = *(const ulonglong2*)(wip + j);
            ulonglong2 wh2 = *(const ulonglong2*)(wh1p + j);
            ulonglong2 h00 = h0p0[j], h01 = h0p1[j], h02 = h0p2[j], h03 = h0p3[j];
            ulonglong2 h10 = h1p0[j], h11 = h1p1[j], h12 = h1p2[j], h13 = h1p3[j];
            fma2(aA0, w0.x, h00.x); fma2(aA0, w0.y, h00.y);
            fma2(aA1, w0.x, h01.x); fma2(aA1, w0.y, h01.y);
            fma2(aA2, w0.x, h02.x); fma2(aA2, w0.y, h02.y);
            fma2(aA3, w0.x, h03.x); fma2(aA3, w0.y, h03.y);
            fma2(aB0, wi2.x, h00.x); fma2(aB0, wi2.y, h00.y);
            fma2(aB1, wi2.x, h01.x); fma2(aB1, wi2.y, h01.y);
            fma2(aB2, wi2.x, h02.x); fma2(aB2, wi2.y, h02.y);
            fma2(aB3, wi2.x, h03.x); fma2(aB3, wi2.y, h03.y);
            fma2(aC0, wh2.x, h10.x); fma2(aC0, wh2.y, h10.y);
            fma2(aC1, wh2.x, h11.x); fma2(aC1, wh2.y, h11.y);
            fma2(aC2, wh2.x, h12.x); fma2(aC2, wh2.y, h12.y);
            fma2(aC3, wh2.x, h13.x); fma2(aC3, wh2.y, h13.y);
        }
        {
            float2 q;
            q = unpk(aA0); redA[w*128 +  0 + l] = q.x + q.y;
            q = unpk(aA1); redA[w*128 + 32 + l] = q.x + q.y;
            q = unpk(aA2); redA[w*128 + 64 + l] = q.x + q.y;
            q = unpk(aA3); redA[w*128 + 96 + l] = q.x + q.y;
            q = unpk(aB0); redB[w*128 +  0 + l] = q.x + q.y;
            q = unpk(aB1); redB[w*128 + 32 + l] = q.x + q.y;
            q = unpk(aB2); redB[w*128 + 64 + l] = q.x + q.y;
            q = unpk(aB3); redB[w*128 + 96 + l] = q.x + q.y;
            q = unpk(aC0); redC[w*128 +  0 + l] = q.x + q.y;
            q = unpk(aC1); redC[w*128 + 32 + l] = q.x + q.y;
            q = unpk(aC2); redC[w*128 + 64 + l] = q.x + q.y;
            q = unpk(aC3); redC[w*128 + 96 + l] = q.x + q.y;
        }
        __syncthreads();

        // Epilogue: 128 threads, one (b,ch) each.
        if (t < 128) {
            float sA = 0.f, sB = 0.f, sC = 0.f;
#pragma unroll
            for (int k = 0; k < 8; k++) {
                sA += redA[k * 128 + t];
                sB += redB[k * 128 + t];
                sC += redC[k * 128 + t];
            }
            float h0n = tanhf(xp0v + bh0v + sA);
            float xp1 = bi1v + sB;
            float h1n = tanhf(xp1 + bh1v + sC);
            hnl0[t] = h0n;
            hnl1[t] = (s > 0) ? h1n : 0.f;
            int b = t >> 5, ch = t & 31;
            size_t oi = (size_t)(b0 + b) * HCC + c0 + ch;
            if (s >= 1)
                out_inp[(size_t)(s - 1) * (BB * HCC) + oi] = h1n;
            if (s == TT - 1) out_hs0[oi] = h0n;
            if (s == TT)     out_hs1[oi] = h1n;
        }
        __syncthreads();

        // Push both slices to ranks w and w+8; one arrive per (CTA, target).
        if (s < TT) {
            float4 v0 = ((const float4*)hnl0)[l];
            float4 v1 = ((const float4*)hnl1)[l];
            if ((s + 1) & 1) {
                st_cluster_f4(h0A1, v0); st_cluster_f4(h1A1, v1);
                st_cluster_f4(h0B1, v0); st_cluster_f4(h1B1, v1);
                __syncwarp();
                if (l == 0) mbar_arrive_remote(mA1);
                else if (l == 1) mbar_arrive_remote(mB1);
            } else {
                st_cluster_f4(h0A0, v0); st_cluster_f4(h1A0, v1);
                st_cluster_f4(h0B0, v0); st_cluster_f4(h1B0, v1);
                __syncwarp();
                if (l == 0) mbar_arrive_remote(mA0);
                else if (l == 1) mbar_arrive_remote(mB0);
            }
        }
    }

    CL_SYNC();
}

// ---------------------------------------------------------------------------
// Output layout: [hs (L,B,HC) | inp (T,B,HC)]
// ---------------------------------------------------------------------------
extern "C" void kernel_launch(void* const* d_in, const int* in_sizes, int n_in,
                              void* d_out, int out_size) {
    const float* x  = (const float*)d_in[0];
    const float* Wi = (const float*)d_in[1];
    const float* bi = (const float*)d_in[2];
    const float* Wh = (const float*)d_in[3];
    const float* bh = (const float*)d_in[4];
    float* out = (float*)d_out;

    // Attribute sets: idempotent, capture-safe, not allocations.
    cudaFuncSetAttribute(fused_kernel,
                         cudaFuncAttributeMaxDynamicSharedMemorySize, FSMEM);
    cudaFuncSetAttribute(fused_kernel,
                         cudaFuncAttributeNonPortableClusterSizeAllowed, 1);

    dim3 pg(HCC / PBN, (TT * BB) / PBM);  // (4, 512)
    proj_kernel<<<pg, 256>>>(x, Wi, bi);  // layer-0 input projection only

    cudaLaunchConfig_t cfg = {};
    cfg.gridDim  = dim3(NCTA, 1, 1);
    cfg.blockDim = dim3(RTH, 1, 1);
    cfg.dynamicSmemBytes = FSMEM;
    cfg.stream = 0;  // legacy default stream (same as <<<>>>), capture-safe
    cudaLaunchAttribute attrs[1];
    attrs[0].id = cudaLaunchAttributeClusterDimension;
    attrs[0].val.clusterDim.x = CS;
    attrs[0].val.clusterDim.y = 1;
    attrs[0].val.clusterDim.z = 1;
    cfg.attrs = attrs;
    cfg.numAttrs = 1;
    cudaLaunchKernelEx(&cfg, fused_kernel, Wi, Wh, bi, bh, out);
}

// round 16
// speedup vs baseline: 1.8802x; 1.1652x over previous
#include <cuda_runtime.h>
#include <math.h>
#include <stdint.h>

// Problem constants
#define TT   2048
#define BB   32
#define ICC  512
#define HCC  512
#define LLL  2

// Fused recurrence: 8 clusters x 16 CTAs. Cluster = 4 batches; CTA = 32 ch.
#define CS    16
#define NCTA  128
#define RTH   256
#define BPG   4
#define CPG   32

// Dynamic smem (bytes): Wi1 pad-129 | staged h0 | staged h1 | red[3][1024]
#define OFF_WI1  0
#define OFF_HS0  66048          // 32 rows * 129 f4 * 16B
#define OFF_HS1  74240
#define OFF_RED  82432
#define FSMEM    94720

// Projection GEMM config
#define PBM 128
#define PBN 128
#define PBK 16
#define PLD (PBM + 4)

// ---------------------------------------------------------------------------
// Scratch (static device globals: allocation-free per harness rules)
// ---------------------------------------------------------------------------
__device__ float g_xproj[(size_t)TT * BB * HCC];
__device__ float g_h0[2][BB * HCC];   // L2-resident h0 ping-pong
__device__ float g_h1[2][BB * HCC];   // L2-resident h1 ping-pong

// ---------------------------------------------------------------------------
// Packed f32x2 helpers
// ---------------------------------------------------------------------------
__device__ __forceinline__ void fma2(unsigned long long& acc,
                                     unsigned long long a, unsigned long long b) {
    asm("fma.rn.f32x2 %0, %1, %2, %0;" : "+l"(acc) : "l"(a), "l"(b));
}
__device__ __forceinline__ unsigned long long dup2(float x) {
    unsigned long long d;
    asm("mov.b64 %0, {%1, %1};" : "=l"(d) : "f"(x));
    return d;
}
__device__ __forceinline__ float2 unpk(unsigned long long v) {
    float2 r;
    asm("mov.b64 {%0, %1}, %2;" : "=f"(r.x), "=f"(r.y) : "l"(v));
    return r;
}

// ---------------------------------------------------------------------------
// Cluster / mbarrier helpers (field-verified R9-R12)
// ---------------------------------------------------------------------------
__device__ __forceinline__ uint32_t smem_u32(const void* p) {
    uint32_t a;
    asm("{ .reg .u64 t; cvta.to.shared.u64 t, %1; cvt.u32.u64 %0, t; }"
        : "=r"(a) : "l"(p));
    return a;
}
__device__ __forceinline__ uint32_t mapa_u32(uint32_t a, uint32_t rank) {
    uint32_t r;
    asm("mapa.shared::cluster.u32 %0, %1, %2;" : "=r"(r) : "r"(a), "r"(rank));
    return r;
}
__device__ __forceinline__ void mbar_init(uint32_t a, uint32_t cnt) {
    asm volatile("mbarrier.init.shared.b64 [%0], %1;" :: "r"(a), "r"(cnt) : "memory");
}
__device__ __forceinline__ void mbar_arrive_remote(uint32_t a) {
    asm volatile("mbarrier.arrive.release.cluster.shared::cluster.b64 _, [%0];"
                 :: "r"(a) : "memory");
}
__device__ __forceinline__ void mbar_wait_parity(uint32_t a, uint32_t parity) {
    uint32_t done;
    asm volatile(
        "{\n\t.reg .pred p;\n\t"
        "mbarrier.try_wait.parity.acquire.cluster.shared::cta.b64 p, [%1], %2;\n\t"
        "selp.b32 %0, 1, 0, p;\n\t}"
        : "=r"(done) : "r"(a), "r"(parity) : "memory");
    if (!done) {
        asm volatile(
            "{\n\t.reg .pred P1;\n\t"
            "W_%=:\n\t"
            "mbarrier.try_wait.parity.acquire.cluster.shared::cta.b64 P1, [%0], %1, 0x989680;\n\t"
            "@P1 bra.uni D_%=;\n\t"
            "bra.uni W_%=;\n\t"
            "D_%=:\n\t}"
            :: "r"(a), "r"(parity) : "memory");
    }
}
#define CL_SYNC() do { \
    asm volatile("barrier.cluster.arrive.aligned;" ::: "memory"); \
    asm volatile("barrier.cluster.wait.aligned;"   ::: "memory"); } while (0)

// ---------------------------------------------------------------------------
// Projection GEMM (R12-proven, FFMA2). Layer 0 only.
// ---------------------------------------------------------------------------
__global__ __launch_bounds__(256, 2)
void proj_kernel(const float* __restrict__ Xin, const float* __restrict__ Wp,
                 const float* __restrict__ bp)
{
    __shared__ float As[PBK][PLD];
    __shared__ float Bs[PBK][PLD];

    const int t  = threadIdx.x;
    const int m0 = blockIdx.y * PBM;
    const int n0 = blockIdx.x * PBN;
    const int lr = t >> 1;
    const int lc = (t & 1) << 3;
    const int tx = t & 15;
    const int ty = t >> 4;

    unsigned long long acc2[8][4];
#pragma unroll
    for (int i = 0; i < 8; i++)
#pragma unroll
        for (int j = 0; j < 4; j++) acc2[i][j] = 0ULL;

    const float* Ag = Xin + (size_t)(m0 + lr) * ICC;
    const float* Bg = Wp  + (size_t)(n0 + lr) * ICC;

    for (int k0 = 0; k0 < ICC; k0 += PBK) {
        float4 a0 = __ldg((const float4*)(Ag + k0 + lc));
        float4 a1 = __ldg((const float4*)(Ag + k0 + lc + 4));
        float4 b0 = __ldg((const float4*)(Bg + k0 + lc));
        float4 b1 = __ldg((const float4*)(Bg + k0 + lc + 4));
        As[lc+0][lr] = a0.x; As[lc+1][lr] = a0.y; As[lc+2][lr] = a0.z; As[lc+3][lr] = a0.w;
        As[lc+4][lr] = a1.x; As[lc+5][lr] = a1.y; As[lc+6][lr] = a1.z; As[lc+7][lr] = a1.w;
        Bs[lc+0][lr] = b0.x; Bs[lc+1][lr] = b0.y; Bs[lc+2][lr] = b0.z; Bs[lc+3][lr] = b0.w;
        Bs[lc+4][lr] = b1.x; Bs[lc+5][lr] = b1.y; Bs[lc+6][lr] = b1.z; Bs[lc+7][lr] = b1.w;
        __syncthreads();
#pragma unroll
        for (int k = 0; k < PBK; k++) {
            float4 am0 = *(const float4*)&As[k][ty * 8];
            float4 am1 = *(const float4*)&As[k][ty * 8 + 4];
            ulonglong2 bu0 = *(const ulonglong2*)&Bs[k][tx * 8];
            ulonglong2 bu1 = *(const ulonglong2*)&Bs[k][tx * 8 + 4];
            float am[8] = {am0.x, am0.y, am0.z, am0.w, am1.x, am1.y, am1.z, am1.w};
#pragma unroll
            for (int i = 0; i < 8; i++) {
                unsigned long long ad = dup2(am[i]);
                fma2(acc2[i][0], ad, bu0.x);
                fma2(acc2[i][1], ad, bu0.y);
                fma2(acc2[i][2], ad, bu1.x);
                fma2(acc2[i][3], ad, bu1.y);
            }
        }
        __syncthreads();
    }

    float4 bv0 = __ldg((const float4*)(bp + n0 + tx * 8));
    float4 bv1 = __ldg((const float4*)(bp + n0 + tx * 8 + 4));
#pragma unroll
    for (int i = 0; i < 8; i++) {
        size_t row = (size_t)(m0 + ty * 8 + i);
        float2 p0 = unpk(acc2[i][0]);
        float2 p1 = unpk(acc2[i][1]);
        float2 p2 = unpk(acc2[i][2]);
        float2 p3 = unpk(acc2[i][3]);
        float4 o0 = make_float4(p0.x + bv0.x, p0.y + bv0.y, p1.x + bv0.z, p1.y + bv0.w);
        float4 o1 = make_float4(p2.x + bv1.x, p2.y + bv1.y, p3.x + bv1.z, p3.y + bv1.w);
        *(float4*)&g_xproj[row * HCC + n0 + tx * 8]     = o0;
        *(float4*)&g_xproj[row * HCC + n0 + tx * 8 + 4] = o1;
    }
}

// ---------------------------------------------------------------------------
// Fused 2-layer recurrence, L2-exchange edition.
// CTA(bg,rank): batches [4bg,+4), channels [32r,+32). Superstep s in [0,TT]:
//   A: h0[s]   = tanh(xp0[s] + bh0 + Wh0 . h0[s-1])     (s < TT)
//   B: xp1     = bi1 + Wi1 . h0[s-1]                    (s >= 1)
//   C: h1[s-1] = tanh(xp1 + bh1 + Wh1 . h1[s-2])        (s >= 1)
// Wh0 + Wh1 in REGISTERS (128 floats/thread); Wi1 in pad-129 smem (B-dot).
// Exchange: producers __stcg slices to global ping-pong g_h0/g_h1 (NO smem-
// port cost), consumers __ldcg 4 KB + restage into local smem. Sync = 16
// remote release-arrives per CTA on the parity mbar (expect=16), exactly the
// R12 double-buffer protocol: a CTA publishes buf s&1 at end of superstep s
// and waits buf (s-1)&1 at the top, so lead is bounded to 1 step.
// ---------------------------------------------------------------------------
__global__ __launch_bounds__(RTH, 1)
void fused_kernel(const float* __restrict__ Wi, const float* __restrict__ Wh,
                  const float* __restrict__ bi, const float* __restrict__ bh,
                  float* __restrict__ out)
{
    extern __shared__ char sm[];
    float4* wi1s = (float4*)(sm + OFF_WI1);      // [32][129] f4, pad-129
    float*  Hs0  = (float*)(sm + OFF_HS0);       // staged h0 [4][512]
    float*  Hs1  = (float*)(sm + OFF_HS1);       // staged h1 [4][512]
    float*  redA = (float*)(sm + OFF_RED);       // [8][128]
    float*  redB = redA + 1024;
    float*  redC = redA + 2048;
    __shared__ __align__(8) unsigned long long mbar[2];

    const int t    = threadIdx.x;
    const int bid  = blockIdx.x;
    const int bg   = bid >> 4;
    const int rank = bid & 15;
    const int b0   = bg * BPG;
    const int c0   = rank * CPG;
    const int w    = t >> 5;        // k-slice [64w, 64w+64)
    const int l    = t & 31;        // channel within CTA
    const int gc   = c0 + l;

    const float* Wh1g = Wh + (size_t)HCC * HCC;
    const float* Wi1g = Wi + (size_t)HCC * ICC;
    float* out_hs0 = out;
    float* out_hs1 = out + BB * HCC;
    float* out_inp = out + (size_t)LLL * BB * HCC;

    // Step-invariant weights -> registers (64 + 64 floats).
    ulonglong2 wr0[16], wr1[16];
    {
        const ulonglong2* p0 = (const ulonglong2*)(Wh   + (size_t)gc * HCC + w * 64);
        const ulonglong2* p1 = (const ulonglong2*)(Wh1g + (size_t)gc * HCC + w * 64);
#pragma unroll
        for (int j = 0; j < 16; j++) { wr0[j] = p0[j]; wr1[j] = p1[j]; }
    }
    // Wi1 slice -> pad-129 smem.
    {
        const float4* si = (const float4*)Wi1g + (size_t)c0 * (HCC / 4);
        for (int idx = t; idx < CPG * (HCC / 4); idx += RTH)
            wi1s[(idx >> 7) * 129 + (idx & 127)] = __ldg(si + idx);
    }
    // Zero staging (serves as h[-1] = 0 for superstep 0).
    for (int i = t; i < BPG * HCC; i += RTH) { Hs0[i] = 0.f; Hs1[i] = 0.f; }
    const uint32_t mb0 = smem_u32(&mbar[0]);
    const uint32_t mb1 = smem_u32(&mbar[1]);
    if (t == 0) { mbar_init(mb0, CS); mbar_init(mb1, CS); }
    __syncthreads();
    CL_SYNC();   // mbarriers live cluster-wide before any remote arrive

    // Remote arrive targets (t < 16: one per cluster rank, incl. self).
    const uint32_t ra0 = (t < CS) ? mapa_u32(mb0, (uint32_t)t) : 0u;
    const uint32_t ra1 = (t < CS) ? mapa_u32(mb1, (uint32_t)t) : 0u;

    // Epilogue constants (t<128): b = t>>5, ch = t&31.
    const int eb = t >> 5, ec = t & 31;
    float bh0v = 0.f, bi1v = 0.f, bh1v = 0.f;
    if (t < 128) {
        bh0v = __ldg(bh + c0 + ec);
        bi1v = __ldg(bi + HCC + c0 + ec);
        bh1v = __ldg(bh + HCC + c0 + ec);
    }
    const size_t eoi = (size_t)(b0 + eb) * HCC + c0 + ec;   // out index (t<128)

    const ulonglong2* wip = (const ulonglong2*)wi1s + (size_t)l * 129 + w * 16;
    int phA = 0, phB = 0;

    for (int s = 0; s <= TT; s++) {
        // Prefetch xproj0[s] (independent of the h chain).
        float xp0v = 0.f;
        if (t < 128 && s < TT)
            xp0v = __ldg(&g_xproj[(size_t)s * (BB * HCC) + eoi]);

        if (s >= 1) {
            const int rb = (s - 1) & 1;
            if (rb == 0) { mbar_wait_parity(mb0, (uint32_t)phA); phA ^= 1; }
            else         { mbar_wait_parity(mb1, (uint32_t)phB); phB ^= 1; }
            // Restage h0/h1 for our 4 batches: 4 LDG.128 + 4 STS per thread.
            const int rb2 = rb;
            const float4* s0 = (const float4*)(g_h0[rb2] + b0 * HCC);
            const float4* s1 = (const float4*)(g_h1[rb2] + b0 * HCC);
            float4 a = __ldcg(s0 + t), b4 = __ldcg(s0 + t + 256);
            float4 c = __ldcg(s1 + t), d4 = __ldcg(s1 + t + 256);
            ((float4*)Hs0)[t] = a; ((float4*)Hs0)[t + 256] = b4;
            ((float4*)Hs1)[t] = c; ((float4*)Hs1)[t + 256] = d4;
        }
        __syncthreads();   // staging visible; also separates prev epilogue's red reads

        // Triple dot: channel l, k in [64w,64w+64), 4 batches. All FFMA2.
        const ulonglong2* h0p = (const ulonglong2*)(Hs0 + w * 64);
        const ulonglong2* h1p = (const ulonglong2*)(Hs1 + w * 64);
        unsigned long long aA0=0,aA1=0,aA2=0,aA3=0;
        unsigned long long aB0=0,aB1=0,aB2=0,aB3=0;
        unsigned long long aC0=0,aC1=0,aC2=0,aC3=0;
#pragma unroll
        for (int j = 0; j < 16; j++) {
            ulonglong2 w0 = wr0[j];
            ulonglong2 w1 = wr1[j];
            ulonglong2 wiv = wip[j];
            ulonglong2 h00 = h0p[j];
            ulonglong2 h01 = h0p[j + 128];   // +512 floats = next batch
            ulonglong2 h02 = h0p[j + 256];
            ulonglong2 h03 = h0p[j + 384];
            ulonglong2 h10 = h1p[j];
            ulonglong2 h11 = h1p[j + 128];
            ulonglong2 h12 = h1p[j + 256];
            ulonglong2 h13 = h1p[j + 384];
            fma2(aA0, w0.x, h00.x); fma2(aA0, w0.y, h00.y);
            fma2(aA1, w0.x, h01.x); fma2(aA1, w0.y, h01.y);
            fma2(aA2, w0.x, h02.x); fma2(aA2, w0.y, h02.y);
            fma2(aA3, w0.x, h03.x); fma2(aA3, w0.y, h03.y);
            fma2(aB0, wiv.x, h00.x); fma2(aB0, wiv.y, h00.y);
            fma2(aB1, wiv.x, h01.x); fma2(aB1, wiv.y, h01.y);
            fma2(aB2, wiv.x, h02.x); fma2(aB2, wiv.y, h02.y);
            fma2(aB3, wiv.x, h03.x); fma2(aB3, wiv.y, h03.y);
            fma2(aC0, w1.x, h10.x); fma2(aC0, w1.y, h10.y);
            fma2(aC1, w1.x, h11.x); fma2(aC1, w1.y, h11.y);
            fma2(aC2, w1.x, h12.x); fma2(aC2, w1.y, h12.y);
            fma2(aC3, w1.x, h13.x); fma2(aC3, w1.y, h13.y);
        }
        {
            float2 q;
            q = unpk(aA0); redA[w*128 +  0 + l] = q.x + q.y;
            q = unpk(aA1); redA[w*128 + 32 + l] = q.x + q.y;
            q = unpk(aA2); redA[w*128 + 64 + l] = q.x + q.y;
            q = unpk(aA3); redA[w*128 + 96 + l] = q.x + q.y;
            q = unpk(aB0); redB[w*128 +  0 + l] = q.x + q.y;
            q = unpk(aB1); redB[w*128 + 32 + l] = q.x + q.y;
            q = unpk(aB2); redB[w*128 + 64 + l] = q.x + q.y;
            q = unpk(aB3); redB[w*128 + 96 + l] = q.x + q.y;
            q = unpk(aC0); redC[w*128 +  0 + l] = q.x + q.y;
            q = unpk(aC1); redC[w*128 + 32 + l] = q.x + q.y;
            q = unpk(aC2); redC[w*128 + 64 + l] = q.x + q.y;
            q = unpk(aC3); redC[w*128 + 96 + l] = q.x + q.y;
        }
        __syncthreads();

        // Epilogue (t<128): reduce, tanh, publish to L2 ping-pong + outputs.
        if (t < 128) {
            float sA = 0.f, sB = 0.f, sC = 0.f;
#pragma unroll
            for (int k = 0; k < 8; k++) {
                sA += redA[k * 128 + t];
                sB += redB[k * 128 + t];
                sC += redC[k * 128 + t];
            }
            float h0n = tanhf(xp0v + bh0v + sA);
            float h1n = (s >= 1) ? tanhf(bi1v + sB + bh1v + sC) : 0.f;
            if (s < TT) {
                __stcg(&g_h0[s & 1][eoi], h0n);
                __stcg(&g_h1[s & 1][eoi], h1n);
            }
            if (s >= 1)
                out_inp[(size_t)(s - 1) * (BB * HCC) + eoi] = h1n;
            if (s == TT - 1) out_hs0[eoi] = h0n;
            if (s == TT)     out_hs1[eoi] = h1n;
        }
        __syncthreads();   // all publishes observed before the arrives

        if (s < TT && t < CS) {
            if (s & 1) mbar_arrive_remote(ra1);
            else       mbar_arrive_remote(ra0);
        }
    }

    CL_SYNC();
}

// ---------------------------------------------------------------------------
// Output layout: [hs (L,B,HC) | inp (T,B,HC)]
// ---------------------------------------------------------------------------
extern "C" void kernel_launch(void* const* d_in, const int* in_sizes, int n_in,
                              void* d_out, int out_size) {
    const float* x  = (const float*)d_in[0];
    const float* Wi = (const float*)d_in[1];
    const float* bi = (const float*)d_in[2];
    const float* Wh = (const float*)d_in[3];
    const float* bh = (const float*)d_in[4];
    float* out = (float*)d_out;

    // Attribute sets: idempotent, capture-safe, not allocations.
    cudaFuncSetAttribute(fused_kernel,
                         cudaFuncAttributeMaxDynamicSharedMemorySize, FSMEM);
    cudaFuncSetAttribute(fused_kernel,
                         cudaFuncAttributeNonPortableClusterSizeAllowed, 1);

    dim3 pg(HCC / PBN, (TT * BB) / PBM);  // (4, 512)
    proj_kernel<<<pg, 256>>>(x, Wi, bi);  // layer-0 input projection only

    cudaLaunchConfig_t cfg = {};
    cfg.gridDim  = dim3(NCTA, 1, 1);
    cfg.blockDim = dim3(RTH, 1, 1);
    cfg.dynamicSmemBytes = FSMEM;
    cfg.stream = 0;
    cudaLaunchAttribute attrs[1];
    attrs[0].id = cudaLaunchAttributeClusterDimension;
    attrs[0].val.clusterDim.x = CS;
    attrs[0].val.clusterDim.y = 1;
    attrs[0].val.clusterDim.z = 1;
    cfg.attrs = attrs;
    cfg.numAttrs = 1;
    cudaLaunchKernelEx(&cfg, fused_kernel, Wi, Wh, bi, bh, out);
}